// round 11
// baseline (speedup 1.0000x reference)
#include <cuda_runtime.h>
#include <cstdint>

#define NCOL  49152                    // OC*IC*KW
#define W2D_ELEMS 37748736ULL          // 2048*2048*3*3
#define GRID  296                      // 2 CTAs/SM persistent
#define NTILES 1024

// ---- scratch ----
__device__ float g_part[64 * 64];
__device__ __align__(16) float g_hidP[256 * 256];   // hidden, mma-A-fragment packed, tf32-rounded

// ---- helpers ----
__device__ __forceinline__ void cp16(void* dst_smem, const void* src) {
    unsigned u = (unsigned)__cvta_generic_to_shared(dst_smem);
    asm volatile("cp.async.cg.shared.global [%0],[%1],16;" :: "r"(u), "l"(src));
}
#define CP_COMMIT() asm volatile("cp.async.commit_group;")
#define CP_WAIT1()  asm volatile("cp.async.wait_group 1;")

__device__ __forceinline__ uint32_t to_tf32(float f) {
    uint32_t u; asm("cvt.rna.tf32.f32 %0,%1;" : "=r"(u) : "f"(f)); return u;
}
#define MMA_TF32(d, a0, a1, a2, a3, b0, b1)                                   \
    asm volatile("mma.sync.aligned.m16n8k8.row.col.f32.tf32.tf32.f32 "        \
        "{%0,%1,%2,%3},{%4,%5,%6,%7},{%8,%9},{%0,%1,%2,%3};"                  \
        : "+f"((d)[0]), "+f"((d)[1]), "+f"((d)[2]), "+f"((d)[3])              \
        : "r"(a0), "r"(a1), "r"(a2), "r"(a3), "r"(b0), "r"(b1))

// ================= prolog kernels =================
__global__ void k_mean(const float* __restrict__ pde, const float* __restrict__ z_bias,
                       const float* __restrict__ u_bias, float* __restrict__ out) {
    int b = blockIdx.x, t = threadIdx.x;
    if (b >= 64) {
        int o = (b - 64) * 256 + t;
        out[W2D_ELEMS + o] = z_bias[o] + u_bias[o];
        return;
    }
    __shared__ float sm[256];
    int d = t & 63, sl = t >> 6;
    float s = 0.f;
    #pragma unroll
    for (int it = 0; it < 4; ++it) s += pde[(b * 16 + sl + it * 4) * 64 + d];
    sm[t] = s;
    __syncthreads();
    if (t < 64) g_part[b * 64 + t] = sm[t] + sm[t + 64] + sm[t + 128] + sm[t + 192];
}

__global__ void k_hid(const float* __restrict__ Z, const float* __restrict__ W1,
                      const float* __restrict__ U1, const float* __restrict__ b1) {
    __shared__ float mean[64];
    __shared__ float zs[64];
    int r = blockIdx.x, t = threadIdx.x;
    if (t < 64) {
        float s = 0.f;
        #pragma unroll
        for (int b = 0; b < 64; ++b) s += g_part[b * 64 + t];
        mean[t] = s * (1.0f / 1024.0f);
        zs[t] = Z[r * 64 + t];
    }
    __syncthreads();
    float acc = b1[t];
    #pragma unroll 8
    for (int d = 0; d < 64; ++d)
        acc += mean[d] * U1[d * 256 + t] + zs[d] * W1[d * 256 + t];
    uint32_t tf = to_tf32(tanhf(acc));
    int rt = r >> 7, m = r & 127, mt = m >> 4, mr = m & 15;
    int g = mr & 7, jb0 = mr >> 3;
    int q = t & 3, jb1 = (t >> 2) & 1, ks = t >> 3;
    int lane = g * 4 + q, j = jb0 + 2 * jb1;
    g_hidP[(((rt * 8 + mt) * 32 + ks) * 32 + lane) * 4 + j] = __uint_as_float(tf);
}

// ================= persistent fused GEMM kernel =================
// CTA: 512 thr = 16 warps (wm = wid&7 row-eighth of 16 rows, wn = wid>>3 col-half).
// CTA tile 128 x 96; warp tile 16 x 48 = 1 m16 x 6 n8 frags (24 acc regs).
// Static persistent schedule (stride GRID); continuous cross-tile cp.async stream.
#define BSTRIDE 104                   // 96 + 8 pad (conflict-free b LDS)
#define BSTAGE  (32 * BSTRIDE)        // 3328 floats
#define STG_STRIDE 56                 // staging row stride (STS conflict-free)
#define SMEM_BYTES ((3 * BSTAGE + 16 * 8 * STG_STRIDE) * 4)

__global__ __launch_bounds__(512, 2) void k_tc(const float* __restrict__ W2,
                                               const float* __restrict__ b2,
                                               const float* __restrict__ unet,
                                               float* __restrict__ out) {
    extern __shared__ float smem[];
    float* Bsm = smem;
    int tid  = threadIdx.x;
    int lane = tid & 31, wid = tid >> 5;
    int wm = wid & 7, wn = wid >> 3;
    float* stgW = smem + 3 * BSTAGE + wid * (8 * STG_STRIDE);
    int row8 = lane >> 2, seg = lane & 3;        // epilogue roles
    int g = row8, q = seg;                        // fragment roles

    int t0 = blockIdx.x;
    int rt = t0 & 1;                              // constant per CTA (GRID even)
    const float* aB = g_hidP + (size_t)(rt * 8 + wm) * 4096;   // this warp's m16 tile

    auto pf = [&](int nt, int c, int st) {
        const float* src = W2 + (size_t)(c * 32) * NCOL + (size_t)(nt >> 1) * 96;
        float* dst = Bsm + st * BSTAGE;
        {   // 768 float4s: 32 rows x 24; 512 threads -> 1st pass all, 2nd pass tid<256
            int idx = tid;
            int row = idx / 24, c4 = idx - row * 24;
            cp16(dst + row * BSTRIDE + c4 * 4, src + (size_t)row * NCOL + c4 * 4);
        }
        if (tid < 256) {
            int idx = 512 + tid;
            int row = idx / 24, c4 = idx - row * 24;
            cp16(dst + row * BSTRIDE + c4 * 4, src + (size_t)row * NCOL + c4 * 4);
        }
    };

    pf(t0, 0, 0); CP_COMMIT();
    pf(t0, 1, 1); CP_COMMIT();
    int stw = 2, strd = 0;

    #pragma unroll 1
    for (int tile = t0; tile < NTILES; tile += GRID) {
        int ct = tile >> 1;
        float acc[6][4];
        #pragma unroll
        for (int u = 0; u < 6; ++u)
            #pragma unroll
            for (int e = 0; e < 4; ++e) acc[u][e] = 0.f;

        #pragma unroll 1
        for (int c = 0; c < 8; ++c) {
            CP_WAIT1();
            __syncthreads();
            int nt = tile, nc = c + 2;
            if (nc >= 8) { nt += GRID; nc -= 8; }
            if (nt < NTILES) pf(nt, nc, stw);
            CP_COMMIT();
            stw = (stw == 2) ? 0 : stw + 1;

            const float* buf = Bsm + strd * BSTAGE;
            #pragma unroll
            for (int ks = 0; ks < 4; ++ks) {
                int kk = c * 4 + ks;
                float4 fa = *(const float4*)(aB + (size_t)(kk * 32 + lane) * 4);
                const float* bk0 = buf + (ks * 8 + q) * BSTRIDE + wn * 48 + g;
                const float* bk1 = bk0 + 4 * BSTRIDE;
                uint32_t br0[6], br1[6];
                #pragma unroll
                for (int u = 0; u < 6; ++u) {
                    br0[u] = __float_as_uint(bk0[u * 8]);   // raw fp32 -> HW tf32 trunc
                    br1[u] = __float_as_uint(bk1[u * 8]);
                }
                uint32_t a0 = __float_as_uint(fa.x), a1 = __float_as_uint(fa.y),
                         a2 = __float_as_uint(fa.z), a3 = __float_as_uint(fa.w);
                #pragma unroll
                for (int u = 0; u < 6; ++u)
                    MMA_TF32(acc[u], a0, a1, a2, a3, br0[u], br1[u]);
            }
            strd = (strd == 2) ? 0 : strd + 1;
        }

        // ---------- epilogue (per-warp, fully static indexing) ----------
        float b2r[12];
        {
            const float* bp = b2 + ct * 96 + wn * 48 + 2 * q;
            #pragma unroll
            for (int u = 0; u < 6; ++u) {
                float2 tv = *(const float2*)(bp + u * 8);
                b2r[2 * u] = tv.x; b2r[2 * u + 1] = tv.y;
            }
        }
        auto coords = [&](int rg, const float4*& up, float4*& op) {
            int r = rt * 128 + wm * 16 + rg * 8 + row8;
            int o  = ((r >> 4) << 7) + (ct >> 2);
            int i0 = ((r & 15) << 7) + ((ct & 3) << 5) + wn * 16;
            size_t nbase = (size_t)o * 2048 + i0;
            up = (const float4*)(unet + nbase * 3 + seg * 12);
            op = (float4*)(out + nbase * 9 + (size_t)seg * 36);
        };
        const float4* up; float4* op;
        coords(0, up, op);
        float4 u0 = __ldcs(up), u1 = __ldcs(up + 1), u2 = __ldcs(up + 2);

        #pragma unroll
        for (int rg = 0; rg < 2; ++rg) {
            #pragma unroll
            for (int u = 0; u < 6; ++u) {
                float2 e;
                e.x = acc[u][rg * 2 + 0] + b2r[2 * u];
                e.y = acc[u][rg * 2 + 1] + b2r[2 * u + 1];
                *(float2*)&stgW[g * STG_STRIDE + u * 8 + 2 * q] = e;
            }
            __syncwarp();
            float4 s0 = *(const float4*)&stgW[row8 * STG_STRIDE + seg * 12 + 0];
            float4 s1 = *(const float4*)&stgW[row8 * STG_STRIDE + seg * 12 + 4];
            float4 s2 = *(const float4*)&stgW[row8 * STG_STRIDE + seg * 12 + 8];
            const float4* upn; float4* opn;
            float4 n0, n1, n2;
            if (rg < 1) {
                coords(rg + 1, upn, opn);
                n0 = __ldcs(upn); n1 = __ldcs(upn + 1); n2 = __ldcs(upn + 2);
            }
            float sv[12] = { s0.x, s0.y, s0.z, s0.w, s1.x, s1.y, s1.z, s1.w,
                             s2.x, s2.y, s2.z, s2.w };
            float uv[12] = { u0.x, u0.y, u0.z, u0.w, u1.x, u1.y, u1.z, u1.w,
                             u2.x, u2.y, u2.z, u2.w };
            #pragma unroll
            for (int jj = 0; jj < 9; ++jj) {
                float v[4];
                #pragma unroll
                for (int e = 0; e < 4; ++e) {
                    int j = jj * 4 + e;
                    int p = j / 9, rem = j - p * 9;
                    int kq = rem / 3, l = rem - kq * 3;
                    v[e] = sv[p * 3 + kq] * uv[p * 3 + l];
                }
                __stcs(op + jj, make_float4(v[0], v[1], v[2], v[3]));
            }
            if (rg < 1) { u0 = n0; u1 = n1; u2 = n2; op = opn; }
            __syncwarp();
        }
    }
}

extern "C" void kernel_launch(void* const* d_in, const int* in_sizes, int n_in,
                              void* d_out, int out_size) {
    const float* Z      = (const float*)d_in[0];
    const float* z_bias = (const float*)d_in[1];
    const float* unet_w = (const float*)d_in[2];
    const float* unet_b = (const float*)d_in[3];
    const float* pde    = (const float*)d_in[4];
    const float* W1     = (const float*)d_in[5];
    const float* U1     = (const float*)d_in[6];
    const float* b1     = (const float*)d_in[7];
    const float* W2     = (const float*)d_in[8];
    const float* b2     = (const float*)d_in[9];
    float* out = (float*)d_out;

    cudaFuncSetAttribute(k_tc, cudaFuncAttributeMaxDynamicSharedMemorySize, SMEM_BYTES);

    k_mean<<<72, 256>>>(pde, z_bias, unet_b, out);
    k_hid<<<256, 256>>>(Z, W1, U1, b1);
    k_tc<<<GRID, 512, SMEM_BYTES>>>(W2, b2, unet_w, out);
}

// round 13
// speedup vs baseline: 1.0684x; 1.0684x over previous
#include <cuda_runtime.h>
#include <cstdint>

#define NCOL  49152                    // OC*IC*KW
#define W2D_ELEMS 37748736ULL          // 2048*2048*3*3
#define GRID  296                      // 2 CTAs/SM persistent
#define NTILES 1024

// ---- scratch ----
__device__ float g_part[64 * 64];
__device__ __align__(16) float g_hidP[256 * 256];   // hidden, mma-A-fragment packed, tf32-rounded

// ---- helpers ----
__device__ __forceinline__ void cp16(void* dst_smem, const void* src) {
    unsigned u = (unsigned)__cvta_generic_to_shared(dst_smem);
    asm volatile("cp.async.cg.shared.global [%0],[%1],16;" :: "r"(u), "l"(src));
}
#define CP_COMMIT() asm volatile("cp.async.commit_group;")
#define CP_WAIT1()  asm volatile("cp.async.wait_group 1;")

__device__ __forceinline__ uint32_t to_tf32(float f) {
    uint32_t u; asm("cvt.rna.tf32.f32 %0,%1;" : "=r"(u) : "f"(f)); return u;
}
#define MMA_TF32(d, a0, a1, a2, a3, b0, b1)                                   \
    asm volatile("mma.sync.aligned.m16n8k8.row.col.f32.tf32.tf32.f32 "        \
        "{%0,%1,%2,%3},{%4,%5,%6,%7},{%8,%9},{%0,%1,%2,%3};"                  \
        : "+f"((d)[0]), "+f"((d)[1]), "+f"((d)[2]), "+f"((d)[3])              \
        : "r"(a0), "r"(a1), "r"(a2), "r"(a3), "r"(b0), "r"(b1))

// ================= prolog kernels =================
__global__ void k_mean(const float* __restrict__ pde, const float* __restrict__ z_bias,
                       const float* __restrict__ u_bias, float* __restrict__ out) {
    int b = blockIdx.x, t = threadIdx.x;
    if (b >= 64) {
        int o = (b - 64) * 256 + t;
        out[W2D_ELEMS + o] = z_bias[o] + u_bias[o];
        return;
    }
    __shared__ float sm[256];
    int d = t & 63, sl = t >> 6;
    float s = 0.f;
    #pragma unroll
    for (int it = 0; it < 4; ++it) s += pde[(b * 16 + sl + it * 4) * 64 + d];
    sm[t] = s;
    __syncthreads();
    if (t < 64) g_part[b * 64 + t] = sm[t] + sm[t + 64] + sm[t + 128] + sm[t + 192];
}

__global__ void k_hid(const float* __restrict__ Z, const float* __restrict__ W1,
                      const float* __restrict__ U1, const float* __restrict__ b1) {
    __shared__ float mean[64];
    __shared__ float zs[64];
    int r = blockIdx.x, t = threadIdx.x;
    if (t < 64) {
        float s = 0.f;
        #pragma unroll
        for (int b = 0; b < 64; ++b) s += g_part[b * 64 + t];
        mean[t] = s * (1.0f / 1024.0f);
        zs[t] = Z[r * 64 + t];
    }
    __syncthreads();
    float acc = b1[t];
    #pragma unroll 8
    for (int d = 0; d < 64; ++d)
        acc += mean[d] * U1[d * 256 + t] + zs[d] * W1[d * 256 + t];
    uint32_t tf = to_tf32(tanhf(acc));
    int rt = r >> 7, m = r & 127, mt = m >> 4, mr = m & 15;
    int g = mr & 7, jb0 = mr >> 3;
    int q = t & 3, jb1 = (t >> 2) & 1, ks = t >> 3;
    int lane = g * 4 + q, j = jb0 + 2 * jb1;
    g_hidP[(((rt * 8 + mt) * 32 + ks) * 32 + lane) * 4 + j] = __uint_as_float(tf);
}

// ================= persistent fused GEMM kernel =================
// R6 structure (verified 107.0us) + unet staged to smem via the cp.async stream.
// FIX vs R12: pfu row coordinate now includes rt (global row, not local).
#define BSTRIDE 104                   // 96 + 8 pad (conflict-free b LDS)
#define BSTAGE  (32 * BSTRIDE)        // 3328 floats
#define USTRIDE 104                   // unet smem row stride
#define U_OFF   (3 * BSTAGE)
#define STG_OFF (U_OFF + 128 * USTRIDE)
#define STG_STRIDE 56                 // staging row stride (STS conflict-free)
#define SMEM_BYTES ((STG_OFF + 8 * 8 * STG_STRIDE) * 4)

__global__ __launch_bounds__(256, 2) void k_tc(const float* __restrict__ W2,
                                               const float* __restrict__ b2,
                                               const float* __restrict__ unet,
                                               float* __restrict__ out) {
    extern __shared__ float smem[];
    float* Bsm = smem;
    float* Usm = smem + U_OFF;
    int tid  = threadIdx.x;
    int lane = tid & 31, wid = tid >> 5;
    int wm = wid & 3, wn = wid >> 2;
    float* stgW = smem + STG_OFF + wid * (8 * STG_STRIDE);
    int row8 = lane >> 2, seg = lane & 3;        // epilogue roles
    int g = row8, q = seg;                        // fragment roles

    int t0 = blockIdx.x;
    int rt = t0 & 1;                              // constant per CTA (GRID even)
    const float* aB0 = g_hidP + (size_t)(rt * 8 + wm * 2) * 4096;
    const float* aB1 = aB0 + 4096;

    auto pf = [&](int nt, int c, int st) {
        const float* src = W2 + (size_t)(c * 32) * NCOL + (size_t)(nt >> 1) * 96;
        float* dst = Bsm + st * BSTAGE;
        #pragma unroll
        for (int i = 0; i < 3; ++i) {
            int idx = i * 256 + tid;            // 0..767 float4s: 32 rows x 24
            int row = idx / 24, c4 = idx - row * 24;
            cp16(dst + row * BSTRIDE + c4 * 4, src + (size_t)row * NCOL + c4 * 4);
        }
    };

    // unet fill: 3072 float4 total (128 rows x 24), spread over chunks 0..5
    auto pfu = [&](int ct, int c) {
        #pragma unroll
        for (int i = 0; i < 2; ++i) {
            int idx = c * 512 + i * 256 + tid;   // 0..3071 exactly over c=0..5
            int row = idx / 24, u4 = idx - row * 24;
            int o  = ((rt * 8 + (row >> 4)) << 7) + (ct >> 2);   // FIXED: include rt
            int i0 = ((row & 15) << 7) + ((ct & 3) << 5);
            cp16(Usm + row * USTRIDE + u4 * 4,
                 unet + ((size_t)o * 2048 + i0) * 3 + u4 * 4);
        }
    };

    pf(t0, 0, 0); CP_COMMIT();
    pf(t0, 1, 1); CP_COMMIT();
    int stw = 2, strd = 0;

    #pragma unroll 1
    for (int tile = t0; tile < NTILES; tile += GRID) {
        int ct = tile >> 1;
        float acc[2][6][4];
        #pragma unroll
        for (int tt = 0; tt < 2; ++tt)
            #pragma unroll
            for (int u = 0; u < 6; ++u)
                #pragma unroll
                for (int e = 0; e < 4; ++e) acc[tt][u][e] = 0.f;

        #pragma unroll 1
        for (int c = 0; c < 8; ++c) {
            CP_WAIT1();
            __syncthreads();
            int nt = tile, nc = c + 2;
            if (nc >= 8) { nt += GRID; nc -= 8; }
            if (nt < NTILES) pf(nt, nc, stw);
            if (c < 6) pfu(ct, c);
            CP_COMMIT();
            stw = (stw == 2) ? 0 : stw + 1;

            const float* buf = Bsm + strd * BSTAGE;
            #pragma unroll
            for (int ks = 0; ks < 4; ++ks) {
                int kk = c * 4 + ks;
                float4 fa0 = *(const float4*)(aB0 + (size_t)(kk * 32 + lane) * 4);
                float4 fa1 = *(const float4*)(aB1 + (size_t)(kk * 32 + lane) * 4);
                const float* bk0 = buf + (ks * 8 + q) * BSTRIDE + wn * 48 + g;
                const float* bk1 = bk0 + 4 * BSTRIDE;
                uint32_t br0[6], br1[6];
                #pragma unroll
                for (int u = 0; u < 6; ++u) {
                    br0[u] = __float_as_uint(bk0[u * 8]);   // raw fp32 -> HW tf32 trunc
                    br1[u] = __float_as_uint(bk1[u * 8]);
                }
                uint32_t a00 = __float_as_uint(fa0.x), a01 = __float_as_uint(fa0.y),
                         a02 = __float_as_uint(fa0.z), a03 = __float_as_uint(fa0.w);
                uint32_t a10 = __float_as_uint(fa1.x), a11 = __float_as_uint(fa1.y),
                         a12 = __float_as_uint(fa1.z), a13 = __float_as_uint(fa1.w);
                #pragma unroll
                for (int u = 0; u < 6; ++u) {
                    MMA_TF32(acc[0][u], a00, a01, a02, a03, br0[u], br1[u]);
                    MMA_TF32(acc[1][u], a10, a11, a12, a13, br0[u], br1[u]);
                }
            }
            strd = (strd == 2) ? 0 : strd + 1;
        }

        // ---------- epilogue (unet from smem; fully static indexing) ----------
        float b2r[12];
        {
            const float* bp = b2 + ct * 96 + wn * 48 + 2 * q;
            #pragma unroll
            for (int u = 0; u < 6; ++u) {
                float2 tv = *(const float2*)(bp + u * 8);
                b2r[2 * u] = tv.x; b2r[2 * u + 1] = tv.y;
            }
        }

        #pragma unroll
        for (int rg = 0; rg < 4; ++rg) {
            int tt = rg >> 1, hi = rg & 1;
            #pragma unroll
            for (int u = 0; u < 6; ++u) {
                float2 e;
                e.x = acc[tt][u][hi * 2 + 0] + b2r[2 * u];
                e.y = acc[tt][u][hi * 2 + 1] + b2r[2 * u + 1];
                *(float2*)&stgW[g * STG_STRIDE + u * 8 + 2 * q] = e;
            }
            __syncwarp();
            float4 s0 = *(const float4*)&stgW[row8 * STG_STRIDE + seg * 12 + 0];
            float4 s1 = *(const float4*)&stgW[row8 * STG_STRIDE + seg * 12 + 4];
            float4 s2 = *(const float4*)&stgW[row8 * STG_STRIDE + seg * 12 + 8];

            int rloc = wm * 32 + rg * 8 + row8;
            const float* sU = Usm + rloc * USTRIDE + wn * 48 + seg * 12;
            float4 u0 = *(const float4*)(sU);
            float4 u1 = *(const float4*)(sU + 4);
            float4 u2 = *(const float4*)(sU + 8);

            int r  = rt * 128 + rloc;
            int o  = ((r >> 4) << 7) + (ct >> 2);
            int i0 = ((r & 15) << 7) + ((ct & 3) << 5) + wn * 16;
            float4* op = (float4*)(out + ((size_t)o * 2048 + i0) * 9 + (size_t)seg * 36);

            float sv[12] = { s0.x, s0.y, s0.z, s0.w, s1.x, s1.y, s1.z, s1.w,
                             s2.x, s2.y, s2.z, s2.w };
            float uv[12] = { u0.x, u0.y, u0.z, u0.w, u1.x, u1.y, u1.z, u1.w,
                             u2.x, u2.y, u2.z, u2.w };
            #pragma unroll
            for (int jj = 0; jj < 9; ++jj) {
                float v[4];
                #pragma unroll
                for (int e = 0; e < 4; ++e) {
                    int j = jj * 4 + e;
                    int p = j / 9, rem = j - p * 9;
                    int kq = rem / 3, l = rem - kq * 3;
                    v[e] = sv[p * 3 + kq] * uv[p * 3 + l];
                }
                __stcs(op + jj, make_float4(v[0], v[1], v[2], v[3]));
            }
            __syncwarp();
        }
    }
}

extern "C" void kernel_launch(void* const* d_in, const int* in_sizes, int n_in,
                              void* d_out, int out_size) {
    const float* Z      = (const float*)d_in[0];
    const float* z_bias = (const float*)d_in[1];
    const float* unet_w = (const float*)d_in[2];
    const float* unet_b = (const float*)d_in[3];
    const float* pde    = (const float*)d_in[4];
    const float* W1     = (const float*)d_in[5];
    const float* U1     = (const float*)d_in[6];
    const float* b1     = (const float*)d_in[7];
    const float* W2     = (const float*)d_in[8];
    const float* b2     = (const float*)d_in[9];
    float* out = (float*)d_out;

    cudaFuncSetAttribute(k_tc, cudaFuncAttributeMaxDynamicSharedMemorySize, SMEM_BYTES);

    k_mean<<<72, 256>>>(pde, z_bias, unet_b, out);
    k_hid<<<256, 256>>>(Z, W1, U1, b1);
    k_tc<<<GRID, 256, SMEM_BYTES>>>(W2, b2, unet_w, out);
}

// round 14
// speedup vs baseline: 1.4950x; 1.3993x over previous
#include <cuda_runtime.h>
#include <cstdint>

#define NCOL  49152                    // OC*IC*KW
#define W2D_ELEMS 37748736ULL          // 2048*2048*3*3
#define GRID  296                      // 2 CTAs/SM persistent
#define NTILES 1024

// ---- scratch ----
__device__ float g_part[64 * 64];
__device__ __align__(16) float g_hidP[256 * 256];   // hidden, mma-A-fragment packed, tf32-rounded

// ---- helpers ----
__device__ __forceinline__ void cp16(void* dst_smem, const void* src) {
    unsigned u = (unsigned)__cvta_generic_to_shared(dst_smem);
    asm volatile("cp.async.cg.shared.global [%0],[%1],16;" :: "r"(u), "l"(src));
}
#define CP_COMMIT() asm volatile("cp.async.commit_group;")
#define CP_WAIT1()  asm volatile("cp.async.wait_group 1;")

__device__ __forceinline__ uint32_t to_tf32(float f) {
    uint32_t u; asm("cvt.rna.tf32.f32 %0,%1;" : "=r"(u) : "f"(f)); return u;
}
#define MMA_TF32(d, a0, a1, a2, a3, b0, b1)                                   \
    asm volatile("mma.sync.aligned.m16n8k8.row.col.f32.tf32.tf32.f32 "        \
        "{%0,%1,%2,%3},{%4,%5,%6,%7},{%8,%9},{%0,%1,%2,%3};"                  \
        : "+f"((d)[0]), "+f"((d)[1]), "+f"((d)[2]), "+f"((d)[3])              \
        : "r"(a0), "r"(a1), "r"(a2), "r"(a3), "r"(b0), "r"(b1))

// ================= prolog kernels =================
__global__ void k_mean(const float* __restrict__ pde, const float* __restrict__ z_bias,
                       const float* __restrict__ u_bias, float* __restrict__ out) {
    int b = blockIdx.x, t = threadIdx.x;
    if (b >= 64) {
        int o = (b - 64) * 256 + t;
        out[W2D_ELEMS + o] = z_bias[o] + u_bias[o];
        return;
    }
    __shared__ float sm[256];
    int d = t & 63, sl = t >> 6;
    float s = 0.f;
    #pragma unroll
    for (int it = 0; it < 4; ++it) s += pde[(b * 16 + sl + it * 4) * 64 + d];
    sm[t] = s;
    __syncthreads();
    if (t < 64) g_part[b * 64 + t] = sm[t] + sm[t + 64] + sm[t + 128] + sm[t + 192];
}

__global__ void k_hid(const float* __restrict__ Z, const float* __restrict__ W1,
                      const float* __restrict__ U1, const float* __restrict__ b1) {
    __shared__ float mean[64];
    __shared__ float zs[64];
    int r = blockIdx.x, t = threadIdx.x;
    if (t < 64) {
        float s = 0.f;
        #pragma unroll
        for (int b = 0; b < 64; ++b) s += g_part[b * 64 + t];
        mean[t] = s * (1.0f / 1024.0f);
        zs[t] = Z[r * 64 + t];
    }
    __syncthreads();
    float acc = b1[t];
    #pragma unroll 8
    for (int d = 0; d < 64; ++d)
        acc += mean[d] * U1[d * 256 + t] + zs[d] * W1[d * 256 + t];
    uint32_t tf = to_tf32(tanhf(acc));
    int rt = r >> 7, m = r & 127, mt = m >> 4, mr = m & 15;
    int g = mr & 7, jb0 = mr >> 3;
    int q = t & 3, jb1 = (t >> 2) & 1, ks = t >> 3;
    int lane = g * 4 + q, j = jb0 + 2 * jb1;
    g_hidP[(((rt * 8 + mt) * 32 + ks) * 32 + lane) * 4 + j] = __uint_as_float(tf);
}

// ================= persistent fused GEMM kernel =================
// R6 mainloop (verified 107.0us) untouched. Epilogue change only: w is staged
// to a per-warp smem out-buffer, then drained with fully-coalesced STG.128
// (store wavefronts per instr: ~32 -> ~4).
#define BSTRIDE 104                   // 96 + 8 pad (conflict-free b LDS)
#define BSTAGE  (32 * BSTRIDE)        // 3328 floats
#define STG_STRIDE 56                 // staging row stride (STS conflict-free)
#define OSTG_OFF (3 * BSTAGE + 8 * 8 * STG_STRIDE)
#define SMEM_BYTES ((OSTG_OFF + 8 * 1152) * 4)

__global__ __launch_bounds__(256, 2) void k_tc(const float* __restrict__ W2,
                                               const float* __restrict__ b2,
                                               const float* __restrict__ unet,
                                               float* __restrict__ out) {
    extern __shared__ float smem[];
    float* Bsm = smem;
    int tid  = threadIdx.x;
    int lane = tid & 31, wid = tid >> 5;
    int wm = wid & 3, wn = wid >> 2;
    float* stgW = smem + 3 * BSTAGE + wid * (8 * STG_STRIDE);
    float* ostW = smem + OSTG_OFF + wid * 1152;   // per-warp w out-stage (8 rows x 144)
    int row8 = lane >> 2, seg = lane & 3;        // epilogue roles
    int g = row8, q = seg;                        // fragment roles

    int t0 = blockIdx.x;
    int rt = t0 & 1;                              // constant per CTA (GRID even)
    const float* aB0 = g_hidP + (size_t)(rt * 8 + wm * 2) * 4096;
    const float* aB1 = aB0 + 4096;

    auto pf = [&](int nt, int c, int st) {
        const float* src = W2 + (size_t)(c * 32) * NCOL + (size_t)(nt >> 1) * 96;
        float* dst = Bsm + st * BSTAGE;
        #pragma unroll
        for (int i = 0; i < 3; ++i) {
            int idx = i * 256 + tid;            // 0..767 float4s: 32 rows x 24
            int row = idx / 24, c4 = idx - row * 24;
            cp16(dst + row * BSTRIDE + c4 * 4, src + (size_t)row * NCOL + c4 * 4);
        }
    };

    pf(t0, 0, 0); CP_COMMIT();
    pf(t0, 1, 1); CP_COMMIT();
    int stw = 2, strd = 0;

    #pragma unroll 1
    for (int tile = t0; tile < NTILES; tile += GRID) {
        int ct = tile >> 1;
        float acc[2][6][4];
        #pragma unroll
        for (int tt = 0; tt < 2; ++tt)
            #pragma unroll
            for (int u = 0; u < 6; ++u)
                #pragma unroll
                for (int e = 0; e < 4; ++e) acc[tt][u][e] = 0.f;

        #pragma unroll 1
        for (int c = 0; c < 8; ++c) {
            CP_WAIT1();
            __syncthreads();
            int nt = tile, nc = c + 2;
            if (nc >= 8) { nt += GRID; nc -= 8; }
            if (nt < NTILES) pf(nt, nc, stw);
            CP_COMMIT();
            stw = (stw == 2) ? 0 : stw + 1;

            const float* buf = Bsm + strd * BSTAGE;
            #pragma unroll
            for (int ks = 0; ks < 4; ++ks) {
                int kk = c * 4 + ks;
                float4 fa0 = *(const float4*)(aB0 + (size_t)(kk * 32 + lane) * 4);
                float4 fa1 = *(const float4*)(aB1 + (size_t)(kk * 32 + lane) * 4);
                const float* bk0 = buf + (ks * 8 + q) * BSTRIDE + wn * 48 + g;
                const float* bk1 = bk0 + 4 * BSTRIDE;
                uint32_t br0[6], br1[6];
                #pragma unroll
                for (int u = 0; u < 6; ++u) {
                    br0[u] = __float_as_uint(bk0[u * 8]);   // raw fp32 -> HW tf32 trunc
                    br1[u] = __float_as_uint(bk1[u * 8]);
                }
                uint32_t a00 = __float_as_uint(fa0.x), a01 = __float_as_uint(fa0.y),
                         a02 = __float_as_uint(fa0.z), a03 = __float_as_uint(fa0.w);
                uint32_t a10 = __float_as_uint(fa1.x), a11 = __float_as_uint(fa1.y),
                         a12 = __float_as_uint(fa1.z), a13 = __float_as_uint(fa1.w);
                #pragma unroll
                for (int u = 0; u < 6; ++u) {
                    MMA_TF32(acc[0][u], a00, a01, a02, a03, br0[u], br1[u]);
                    MMA_TF32(acc[1][u], a10, a11, a12, a13, br0[u], br1[u]);
                }
            }
            strd = (strd == 2) ? 0 : strd + 1;
        }

        // ---------- epilogue ----------
        float b2r[12];
        {
            const float* bp = b2 + ct * 96 + wn * 48 + 2 * q;
            #pragma unroll
            for (int u = 0; u < 6; ++u) {
                float2 tv = *(const float2*)(bp + u * 8);
                b2r[2 * u] = tv.x; b2r[2 * u + 1] = tv.y;
            }
        }
        auto ucoords = [&](int rg) {
            int r = rt * 128 + wm * 32 + rg * 8 + row8;
            int o  = ((r >> 4) << 7) + (ct >> 2);
            int i0 = ((r & 15) << 7) + ((ct & 3) << 5) + wn * 16;
            size_t nbase = (size_t)o * 2048 + i0;
            return (const float4*)(unet + nbase * 3 + seg * 12);
        };
        const float4* up = ucoords(0);
        float4 u0 = __ldcs(up), u1 = __ldcs(up + 1), u2 = __ldcs(up + 2);

        #pragma unroll
        for (int rg = 0; rg < 4; ++rg) {
            int tt = rg >> 1, hi = rg & 1;
            #pragma unroll
            for (int u = 0; u < 6; ++u) {
                float2 e;
                e.x = acc[tt][u][hi * 2 + 0] + b2r[2 * u];
                e.y = acc[tt][u][hi * 2 + 1] + b2r[2 * u + 1];
                *(float2*)&stgW[g * STG_STRIDE + u * 8 + 2 * q] = e;
            }
            __syncwarp();
            float4 s0 = *(const float4*)&stgW[row8 * STG_STRIDE + seg * 12 + 0];
            float4 s1 = *(const float4*)&stgW[row8 * STG_STRIDE + seg * 12 + 4];
            float4 s2 = *(const float4*)&stgW[row8 * STG_STRIDE + seg * 12 + 8];
            const float4* upn;
            float4 n0, n1, n2;
            if (rg < 3) {
                upn = ucoords(rg + 1);
                n0 = __ldcs(upn); n1 = __ldcs(upn + 1); n2 = __ldcs(upn + 2);
            }
            float sv[12] = { s0.x, s0.y, s0.z, s0.w, s1.x, s1.y, s1.z, s1.w,
                             s2.x, s2.y, s2.z, s2.w };
            float uv[12] = { u0.x, u0.y, u0.z, u0.w, u1.x, u1.y, u1.z, u1.w,
                             u2.x, u2.y, u2.z, u2.w };
            // stage w into per-warp out-buffer (conflict-free STS.128)
            #pragma unroll
            for (int jj = 0; jj < 9; ++jj) {
                float v[4];
                #pragma unroll
                for (int e = 0; e < 4; ++e) {
                    int j = jj * 4 + e;
                    int p = j / 9, rem = j - p * 9;
                    int kq = rem / 3, l = rem - kq * 3;
                    v[e] = sv[p * 3 + kq] * uv[p * 3 + l];
                }
                *(float4*)&ostW[row8 * 144 + seg * 36 + jj * 4] =
                    make_float4(v[0], v[1], v[2], v[3]);
            }
            __syncwarp();
            // coalesced drain: per row, 512B by full warp + 64B by lanes 0..3
            #pragma unroll
            for (int row = 0; row < 8; ++row) {
                int r = rt * 128 + wm * 32 + rg * 8 + row;
                int o  = ((r >> 4) << 7) + (ct >> 2);
                int i0 = ((r & 15) << 7) + ((ct & 3) << 5) + wn * 16;
                float4* gb = (float4*)(out + ((size_t)o * 2048 + i0) * 9);
                float4 tA = *(const float4*)&ostW[row * 144 + lane * 4];
                __stcs(gb + lane, tA);
                if (lane < 4) {
                    float4 tB = *(const float4*)&ostW[row * 144 + 128 + lane * 4];
                    __stcs(gb + 32 + lane, tB);
                }
            }
            if (rg < 3) { u0 = n0; u1 = n1; u2 = n2; }
            __syncwarp();
        }
    }
}

extern "C" void kernel_launch(void* const* d_in, const int* in_sizes, int n_in,
                              void* d_out, int out_size) {
    const float* Z      = (const float*)d_in[0];
    const float* z_bias = (const float*)d_in[1];
    const float* unet_w = (const float*)d_in[2];
    const float* unet_b = (const float*)d_in[3];
    const float* pde    = (const float*)d_in[4];
    const float* W1     = (const float*)d_in[5];
    const float* U1     = (const float*)d_in[6];
    const float* b1     = (const float*)d_in[7];
    const float* W2     = (const float*)d_in[8];
    const float* b2     = (const float*)d_in[9];
    float* out = (float*)d_out;

    cudaFuncSetAttribute(k_tc, cudaFuncAttributeMaxDynamicSharedMemorySize, SMEM_BYTES);

    k_mean<<<72, 256>>>(pde, z_bias, unet_b, out);
    k_hid<<<256, 256>>>(Z, W1, U1, b1);
    k_tc<<<GRID, 256, SMEM_BYTES>>>(W2, b2, unet_w, out);
}

// round 15
// speedup vs baseline: 1.5011x; 1.0041x over previous
#include <cuda_runtime.h>
#include <cstdint>

#define NCOL  49152                    // OC*IC*KW
#define W2D_ELEMS 37748736ULL          // 2048*2048*3*3
#define GRID  296                      // 2 CTAs/SM persistent
#define NTILES 1024

// ---- scratch ----
__device__ float g_part[64 * 64];
__device__ __align__(16) float g_hidP[256 * 256];   // hidden, mma-A-fragment packed, tf32-rounded

// ---- helpers ----
__device__ __forceinline__ void cp16(void* dst_smem, const void* src) {
    unsigned u = (unsigned)__cvta_generic_to_shared(dst_smem);
    asm volatile("cp.async.cg.shared.global [%0],[%1],16;" :: "r"(u), "l"(src));
}
#define CP_COMMIT() asm volatile("cp.async.commit_group;")
#define CP_WAIT1()  asm volatile("cp.async.wait_group 1;")

__device__ __forceinline__ uint32_t to_tf32(float f) {
    uint32_t u; asm("cvt.rna.tf32.f32 %0,%1;" : "=r"(u) : "f"(f)); return u;
}
#define MMA_TF32(d, a0, a1, a2, a3, b0, b1)                                   \
    asm volatile("mma.sync.aligned.m16n8k8.row.col.f32.tf32.tf32.f32 "        \
        "{%0,%1,%2,%3},{%4,%5,%6,%7},{%8,%9},{%0,%1,%2,%3};"                  \
        : "+f"((d)[0]), "+f"((d)[1]), "+f"((d)[2]), "+f"((d)[3])              \
        : "r"(a0), "r"(a1), "r"(a2), "r"(a3), "r"(b0), "r"(b1))

// ================= prolog kernels =================
__global__ void k_mean(const float* __restrict__ pde, const float* __restrict__ z_bias,
                       const float* __restrict__ u_bias, float* __restrict__ out) {
    int b = blockIdx.x, t = threadIdx.x;
    if (b >= 64) {
        int o = (b - 64) * 256 + t;
        out[W2D_ELEMS + o] = z_bias[o] + u_bias[o];
        return;
    }
    __shared__ float sm[256];
    int d = t & 63, sl = t >> 6;
    float s = 0.f;
    #pragma unroll
    for (int it = 0; it < 4; ++it) s += pde[(b * 16 + sl + it * 4) * 64 + d];
    sm[t] = s;
    __syncthreads();
    if (t < 64) g_part[b * 64 + t] = sm[t] + sm[t + 64] + sm[t + 128] + sm[t + 192];
}

__global__ void k_hid(const float* __restrict__ Z, const float* __restrict__ W1,
                      const float* __restrict__ U1, const float* __restrict__ b1) {
    __shared__ float mean[64];
    __shared__ float zs[64];
    int r = blockIdx.x, t = threadIdx.x;
    if (t < 64) {
        float s = 0.f;
        #pragma unroll
        for (int b = 0; b < 64; ++b) s += g_part[b * 64 + t];
        mean[t] = s * (1.0f / 1024.0f);
        zs[t] = Z[r * 64 + t];
    }
    __syncthreads();
    float acc = b1[t];
    #pragma unroll 8
    for (int d = 0; d < 64; ++d)
        acc += mean[d] * U1[d * 256 + t] + zs[d] * W1[d * 256 + t];
    uint32_t tf = to_tf32(tanhf(acc));
    int rt = r >> 7, m = r & 127, mt = m >> 4, mr = m & 15;
    int g = mr & 7, jb0 = mr >> 3;
    int q = t & 3, jb1 = (t >> 2) & 1, ks = t >> 3;
    int lane = g * 4 + q, j = jb0 + 2 * jb1;
    g_hidP[(((rt * 8 + mt) * 32 + ks) * 32 + lane) * 4 + j] = __uint_as_float(tf);
}

// ================= persistent fused GEMM kernel =================
// Mainloop byte-identical to the 86.9us winner. Epilogue: stores already
// smem-coalesced; NOW unet loads are also cooperatively loaded (linear idx
// mapping -> ~5 wavefronts/instr instead of ~16) and staged through smem.
#define BSTRIDE 104                   // 96 + 8 pad (conflict-free b LDS)
#define BSTAGE  (32 * BSTRIDE)        // 3328 floats
#define STG_STRIDE 56                 // staging row stride (STS conflict-free)
#define OSTG_OFF (3 * BSTAGE + 8 * 8 * STG_STRIDE)
#define USM_OFF  (OSTG_OFF + 8 * 1152)
#define SMEM_BYTES ((USM_OFF + 8 * 384) * 4)

__global__ __launch_bounds__(256, 2) void k_tc(const float* __restrict__ W2,
                                               const float* __restrict__ b2,
                                               const float* __restrict__ unet,
                                               float* __restrict__ out) {
    extern __shared__ float smem[];
    float* Bsm = smem;
    int tid  = threadIdx.x;
    int lane = tid & 31, wid = tid >> 5;
    int wm = wid & 3, wn = wid >> 2;
    float* stgW = smem + 3 * BSTAGE + wid * (8 * STG_STRIDE);
    float* ostW = smem + OSTG_OFF + wid * 1152;   // per-warp w out-stage (8 rows x 144)
    float* uSmW = smem + USM_OFF + wid * 384;     // per-warp unet stage (8 rows x 48)
    int row8 = lane >> 2, seg = lane & 3;        // epilogue roles
    int g = row8, q = seg;                        // fragment roles

    int t0 = blockIdx.x;
    int rt = t0 & 1;                              // constant per CTA (GRID even)
    const float* aB0 = g_hidP + (size_t)(rt * 8 + wm * 2) * 4096;
    const float* aB1 = aB0 + 4096;

    auto pf = [&](int nt, int c, int st) {
        const float* src = W2 + (size_t)(c * 32) * NCOL + (size_t)(nt >> 1) * 96;
        float* dst = Bsm + st * BSTAGE;
        #pragma unroll
        for (int i = 0; i < 3; ++i) {
            int idx = i * 256 + tid;            // 0..767 float4s: 32 rows x 24
            int row = idx / 24, c4 = idx - row * 24;
            cp16(dst + row * BSTRIDE + c4 * 4, src + (size_t)row * NCOL + c4 * 4);
        }
    };

    pf(t0, 0, 0); CP_COMMIT();
    pf(t0, 1, 1); CP_COMMIT();
    int stw = 2, strd = 0;

    #pragma unroll 1
    for (int tile = t0; tile < NTILES; tile += GRID) {
        int ct = tile >> 1;
        float acc[2][6][4];
        #pragma unroll
        for (int tt = 0; tt < 2; ++tt)
            #pragma unroll
            for (int u = 0; u < 6; ++u)
                #pragma unroll
                for (int e = 0; e < 4; ++e) acc[tt][u][e] = 0.f;

        #pragma unroll 1
        for (int c = 0; c < 8; ++c) {
            CP_WAIT1();
            __syncthreads();
            int nt = tile, nc = c + 2;
            if (nc >= 8) { nt += GRID; nc -= 8; }
            if (nt < NTILES) pf(nt, nc, stw);
            CP_COMMIT();
            stw = (stw == 2) ? 0 : stw + 1;

            const float* buf = Bsm + strd * BSTAGE;
            #pragma unroll
            for (int ks = 0; ks < 4; ++ks) {
                int kk = c * 4 + ks;
                float4 fa0 = *(const float4*)(aB0 + (size_t)(kk * 32 + lane) * 4);
                float4 fa1 = *(const float4*)(aB1 + (size_t)(kk * 32 + lane) * 4);
                const float* bk0 = buf + (ks * 8 + q) * BSTRIDE + wn * 48 + g;
                const float* bk1 = bk0 + 4 * BSTRIDE;
                uint32_t br0[6], br1[6];
                #pragma unroll
                for (int u = 0; u < 6; ++u) {
                    br0[u] = __float_as_uint(bk0[u * 8]);   // raw fp32 -> HW tf32 trunc
                    br1[u] = __float_as_uint(bk1[u * 8]);
                }
                uint32_t a00 = __float_as_uint(fa0.x), a01 = __float_as_uint(fa0.y),
                         a02 = __float_as_uint(fa0.z), a03 = __float_as_uint(fa0.w);
                uint32_t a10 = __float_as_uint(fa1.x), a11 = __float_as_uint(fa1.y),
                         a12 = __float_as_uint(fa1.z), a13 = __float_as_uint(fa1.w);
                #pragma unroll
                for (int u = 0; u < 6; ++u) {
                    MMA_TF32(acc[0][u], a00, a01, a02, a03, br0[u], br1[u]);
                    MMA_TF32(acc[1][u], a10, a11, a12, a13, br0[u], br1[u]);
                }
            }
            strd = (strd == 2) ? 0 : strd + 1;
        }

        // ---------- epilogue ----------
        float b2r[12];
        {
            const float* bp = b2 + ct * 96 + wn * 48 + 2 * q;
            #pragma unroll
            for (int u = 0; u < 6; ++u) {
                float2 tv = *(const float2*)(bp + u * 8);
                b2r[2 * u] = tv.x; b2r[2 * u + 1] = tv.y;
            }
        }
        // cooperative, near-coalesced unet load for one rg (linear idx mapping)
        auto uload = [&](int rg, float4* v) {
            int rbase = rt * 128 + wm * 32 + rg * 8;
            int o = ((rbase >> 4) << 7) + (ct >> 2);
            #pragma unroll
            for (int it = 0; it < 3; ++it) {
                int idx = it * 32 + lane;            // 0..95
                int row = idx / 12, cc = idx - row * 12;
                int r = rbase + row;
                int i0 = ((r & 15) << 7) + ((ct & 3) << 5) + wn * 16;
                v[it] = __ldcs((const float4*)(unet + ((size_t)o * 2048 + i0) * 3) + cc);
            }
        };
        float4 uvr[3];
        uload(0, uvr);

        #pragma unroll
        for (int rg = 0; rg < 4; ++rg) {
            int tt = rg >> 1, hi = rg & 1;
            // stage held unet regs (contiguous STS: addr = idx*4)
            #pragma unroll
            for (int it = 0; it < 3; ++it)
                *(float4*)&uSmW[(it * 32 + lane) * 4] = uvr[it];
            #pragma unroll
            for (int u = 0; u < 6; ++u) {
                float2 e;
                e.x = acc[tt][u][hi * 2 + 0] + b2r[2 * u];
                e.y = acc[tt][u][hi * 2 + 1] + b2r[2 * u + 1];
                *(float2*)&stgW[g * STG_STRIDE + u * 8 + 2 * q] = e;
            }
            __syncwarp();
            if (rg < 3) uload(rg + 1, uvr);         // issue next rg's loads early
            float4 s0 = *(const float4*)&stgW[row8 * STG_STRIDE + seg * 12 + 0];
            float4 s1 = *(const float4*)&stgW[row8 * STG_STRIDE + seg * 12 + 4];
            float4 s2 = *(const float4*)&stgW[row8 * STG_STRIDE + seg * 12 + 8];
            float4 u0 = *(const float4*)&uSmW[row8 * 48 + seg * 12 + 0];
            float4 u1 = *(const float4*)&uSmW[row8 * 48 + seg * 12 + 4];
            float4 u2 = *(const float4*)&uSmW[row8 * 48 + seg * 12 + 8];
            float sv[12] = { s0.x, s0.y, s0.z, s0.w, s1.x, s1.y, s1.z, s1.w,
                             s2.x, s2.y, s2.z, s2.w };
            float uv[12] = { u0.x, u0.y, u0.z, u0.w, u1.x, u1.y, u1.z, u1.w,
                             u2.x, u2.y, u2.z, u2.w };
            // stage w into per-warp out-buffer (conflict-free STS.128)
            #pragma unroll
            for (int jj = 0; jj < 9; ++jj) {
                float v[4];
                #pragma unroll
                for (int e = 0; e < 4; ++e) {
                    int j = jj * 4 + e;
                    int p = j / 9, rem = j - p * 9;
                    int kq = rem / 3, l = rem - kq * 3;
                    v[e] = sv[p * 3 + kq] * uv[p * 3 + l];
                }
                *(float4*)&ostW[row8 * 144 + seg * 36 + jj * 4] =
                    make_float4(v[0], v[1], v[2], v[3]);
            }
            __syncwarp();
            // coalesced drain: per row, 512B by full warp + 64B by lanes 0..3
            #pragma unroll
            for (int row = 0; row < 8; ++row) {
                int r = rt * 128 + wm * 32 + rg * 8 + row;
                int o  = ((r >> 4) << 7) + (ct >> 2);
                int i0 = ((r & 15) << 7) + ((ct & 3) << 5) + wn * 16;
                float4* gb = (float4*)(out + ((size_t)o * 2048 + i0) * 9);
                float4 tA = *(const float4*)&ostW[row * 144 + lane * 4];
                __stcs(gb + lane, tA);
                if (lane < 4) {
                    float4 tB = *(const float4*)&ostW[row * 144 + 128 + lane * 4];
                    __stcs(gb + 32 + lane, tB);
                }
            }
            __syncwarp();
        }
    }
}

extern "C" void kernel_launch(void* const* d_in, const int* in_sizes, int n_in,
                              void* d_out, int out_size) {
    const float* Z      = (const float*)d_in[0];
    const float* z_bias = (const float*)d_in[1];
    const float* unet_w = (const float*)d_in[2];
    const float* unet_b = (const float*)d_in[3];
    const float* pde    = (const float*)d_in[4];
    const float* W1     = (const float*)d_in[5];
    const float* U1     = (const float*)d_in[6];
    const float* b1     = (const float*)d_in[7];
    const float* W2     = (const float*)d_in[8];
    const float* b2     = (const float*)d_in[9];
    float* out = (float*)d_out;

    cudaFuncSetAttribute(k_tc, cudaFuncAttributeMaxDynamicSharedMemorySize, SMEM_BYTES);

    k_mean<<<72, 256>>>(pde, z_bias, unet_b, out);
    k_hid<<<256, 256>>>(Z, W1, U1, b1);
    k_tc<<<GRID, 256, SMEM_BYTES>>>(W2, b2, unet_w, out);
}